// round 5
// baseline (speedup 1.0000x reference)
#include <cuda_runtime.h>

#define M 8192
#define NT 25          // Taylor terms n = 0..24
#define NGROUPS 3072   // 3 matrices * (8192/8) row-groups
#define GRID_PERSIST 888  // 148 SMs * 6 resident blocks

// Scratch (allocation-free rule: __device__ globals)
__device__ float g_q[M], g_k[M], g_v[M];
__device__ float g_C[NT], g_D[NT];
__device__ int   g_ctr = 0;   // work-queue counter; reset by finalize_kernel

// ---------------------------------------------------------------------------
// K1: fused triple GEMV  y = W @ x + b, persistent-block version.
// Grid = 888 (exactly one full wave at 6 blocks/SM). Blocks pull 8-row work
// groups off a global atomic counter -> no wave-quantization tail.
// Inner loop identical to R2 (82.9% DRAM proven).
// Block 0 also zero-inits g_C/g_D for the moments kernel (stream-ordered).
// ---------------------------------------------------------------------------
__global__ void __launch_bounds__(256) gemv3_kernel(
    const float* __restrict__ x,
    const float* __restrict__ Wq, const float* __restrict__ bq,
    const float* __restrict__ Wk, const float* __restrict__ bk,
    const float* __restrict__ Wv, const float* __restrict__ bv)
{
    __shared__ float4 sx[M / 4];          // 32 KB
    __shared__ int    s_g;
    const int tid = threadIdx.x;

    if (blockIdx.x == 0 && tid < NT) { g_C[tid] = 0.f; g_D[tid] = 0.f; }

    const float4* x4 = reinterpret_cast<const float4*>(x);
#pragma unroll
    for (int i = 0; i < (M / 4) / 256; i++)
        sx[tid + i * 256] = x4[tid + i * 256];

    const int warp = tid >> 5;
    const int lane = tid & 31;

    for (;;) {
        if (tid == 0) s_g = atomicAdd(&g_ctr, 1);
        __syncthreads();                  // also covers the sx staging on iter 0
        const int g = s_g;
        __syncthreads();                  // everyone has read s_g before next overwrite
        if (g >= NGROUPS) break;

        const int mat = g >> 10;          // 0:q 1:k 2:v
        const int blk = g & 1023;
        const int row = blk * 8 + warp;

        const float* W;
        const float* b;
        float*       y;
        if (mat == 0)      { W = Wq; b = bq; y = g_q; }
        else if (mat == 1) { W = Wk; b = bk; y = g_k; }
        else               { W = Wv; b = bv; y = g_v; }

        const float4* Wr = reinterpret_cast<const float4*>(W + (size_t)row * M);

        float sum = 0.f;
#pragma unroll 8
        for (int c = lane; c < M / 4; c += 32) {
            float4 w  = Wr[c];
            float4 xx = sx[c];
            sum += w.x * xx.x + w.y * xx.y + w.z * xx.z + w.w * xx.w;
        }
#pragma unroll
        for (int o = 16; o; o >>= 1)
            sum += __shfl_xor_sync(0xffffffffu, sum, o);
        if (lane == 0)
            y[row] = sum + b[row];
    }
}

// ---------------------------------------------------------------------------
// K2: moment accumulation, 32 blocks x 256 threads (one j per thread).
//   C_n = sum_j k_j^n / n!      D_n = sum_j k_j^n * v_j / n!
// Warp shuffle reduce -> shared atomics (8-way) -> global atomics (32-way).
// ---------------------------------------------------------------------------
__global__ void __launch_bounds__(256) moments_kernel()
{
    __shared__ float sC[NT], sD[NT];
    const int tid = threadIdx.x;
    if (tid < NT) { sC[tid] = 0.f; sD[tid] = 0.f; }
    __syncthreads();

    const int j = blockIdx.x * 256 + tid;
    const float k = g_k[j];
    const float v = g_v[j];

    float C[NT], D[NT];
    float term = 1.f;                     // k^n / n!
#pragma unroll
    for (int n = 0; n < NT; n++) {
        C[n] = term;
        D[n] = term * v;
        term *= k * (1.0f / (float)(n + 1));
    }

#pragma unroll
    for (int n = 0; n < NT; n++) {
#pragma unroll
        for (int o = 16; o; o >>= 1) {
            C[n] += __shfl_xor_sync(0xffffffffu, C[n], o);
            D[n] += __shfl_xor_sync(0xffffffffu, D[n], o);
        }
    }
    if ((tid & 31) == 0) {
#pragma unroll
        for (int n = 0; n < NT; n++) {
            atomicAdd(&sC[n], C[n]);
            atomicAdd(&sD[n], D[n]);
        }
    }
    __syncthreads();
    if (tid < NT) {
        atomicAdd(&g_C[tid], sC[tid]);
        atomicAdd(&g_D[tid], sD[tid]);
    }
}

// ---------------------------------------------------------------------------
// K3: per-row softmax-weighted average via Horner evaluation of the two
// moment polynomials.  out[i] = S1(a_i) / S0(a_i),  a_i = q_i / 32.
// Also resets the persistent-gemv work counter for the next graph replay.
// ---------------------------------------------------------------------------
__global__ void __launch_bounds__(256) finalize_kernel(float* __restrict__ out)
{
    __shared__ float sC[NT], sD[NT];
    const int tid = threadIdx.x;
    if (blockIdx.x == 0 && tid == 0) g_ctr = 0;   // re-arm work queue
    if (tid < NT) { sC[tid] = g_C[tid]; sD[tid] = g_D[tid]; }
    __syncthreads();

    const int i = blockIdx.x * 256 + tid;
    const float a = g_q[i] * 0.03125f;    // 1/sqrt(1024) = 1/32

    float s0 = sC[NT - 1];
    float s1 = sD[NT - 1];
#pragma unroll
    for (int n = NT - 2; n >= 0; n--) {
        s0 = fmaf(s0, a, sC[n]);
        s1 = fmaf(s1, a, sD[n]);
    }
    out[i] = s1 / s0;
}

// ---------------------------------------------------------------------------
extern "C" void kernel_launch(void* const* d_in, const int* in_sizes, int n_in,
                              void* d_out, int out_size)
{
    const float* x  = (const float*)d_in[0];
    const float* Wq = (const float*)d_in[1];
    const float* bq = (const float*)d_in[2];
    const float* Wk = (const float*)d_in[3];
    const float* bk = (const float*)d_in[4];
    const float* Wv = (const float*)d_in[5];
    const float* bv = (const float*)d_in[6];

    gemv3_kernel<<<GRID_PERSIST, 256>>>(x, Wq, bq, Wk, bk, Wv, bv);
    moments_kernel<<<32, 256>>>();
    finalize_kernel<<<M / 256, 256>>>((float*)d_out);
}